// round 3
// baseline (speedup 1.0000x reference)
#include <cuda_runtime.h>

// E8 quantizer, closed form.
//
// All 240 E8 roots have ||c||^2 = 2, so softmax(-(||x||^2 - 2 x.c + ||c||^2)/T)
// == softmax(beta * x.c) with beta = 2/T = 2/0.3.  Root structure factorizes:
//
//  Type-1 (112 roots: +-1 at i, +-1 at j, i<j):
//     A_i = 2cosh(beta x_i), B_i = 2sinh(beta x_i)
//     weight sum  = sum_{i<j} A_i A_j = 0.5 * sum_d A_d * exclSum_d(A)
//     numerator_d = B_d * exclSum_d(A)
//  Type-2 (128 roots: (+-1/2)^8, even parity):
//     a_i = 2cosh(beta x_i/2), b_i = 2sinh(beta x_i/2)
//     weight sum  = (prod a + prod b)/2
//     numerator_d = ( b_d * exclProd_d(a) + a_d * exclProd_d(b) ) / 4
//  A = a^2 - 2, B = a*b  -> 16 EX2 + 1 RCP per point.
//
// Exclusive sums/products via binary tree (sibling combines only): all-positive
// adds and sign-safe muls -> no catastrophic cancellation when one exp wins.
// Roots come in +- pairs => max dot >= 0 => denom >= 1, no max-shift needed.
//
// R2 lesson: 1 point/thread (2-pt version spilled to local and de-coalesced).
// This round: tree math + launch_bounds(256,6) for occupancy + streaming
// cache hints (read-once input, write-once output).

#define BETA_HALF_LOG2E 4.8089834696568576f   // (2/0.3)/2 * log2(e)

__device__ __forceinline__ float ex2_approx(float x) {
    float y;
    asm("ex2.approx.ftz.f32 %0, %1;" : "=f"(y) : "f"(x));
    return y;
}

__device__ __forceinline__ float rcp_approx(float x) {
    float y;
    asm("rcp.approx.ftz.f32 %0, %1;" : "=f"(y) : "f"(x));
    return y;
}

__global__ void __launch_bounds__(256, 6) e8_quantize_kernel(
    const float4* __restrict__ x4, float4* __restrict__ o4, int n)
{
    int p = blockIdx.x * blockDim.x + threadIdx.x;
    if (p >= n) return;

    float4 v0 = __ldcs(&x4[2 * p + 0]);
    float4 v1 = __ldcs(&x4[2 * p + 1]);
    float xi[8] = {v0.x, v0.y, v0.z, v0.w, v1.x, v1.y, v1.z, v1.w};

    float a[8], b[8], A[8];
#pragma unroll
    for (int i = 0; i < 8; i++) {
        float t  = xi[i] * BETA_HALF_LOG2E;
        float hp = ex2_approx(t);
        float hn = ex2_approx(-t);
        a[i] = hp + hn;
        b[i] = hp - hn;
        A[i] = fmaf(a[i], a[i], -2.0f);
    }

    // ---- exclusive sums of A via tree (all positive, no cancellation) ----
    float s01 = A[0] + A[1], s23 = A[2] + A[3], s45 = A[4] + A[5], s67 = A[6] + A[7];
    float s0123 = s01 + s23, s4567 = s45 + s67;
    float ES01 = s4567 + s23, ES23 = s4567 + s01;
    float ES45 = s0123 + s67, ES67 = s0123 + s45;
    float eS[8];
    eS[0] = ES01 + A[1]; eS[1] = ES01 + A[0];
    eS[2] = ES23 + A[3]; eS[3] = ES23 + A[2];
    eS[4] = ES45 + A[5]; eS[5] = ES45 + A[4];
    eS[6] = ES67 + A[7]; eS[7] = ES67 + A[6];

    // D1 = sum_{i<j} A_i A_j = 0.5 * sum_d A_d * eS_d
    float D1 = 0.0f;
#pragma unroll
    for (int d = 0; d < 8; d++) D1 = fmaf(A[d], eS[d], D1);
    D1 *= 0.5f;

    // ---- exclusive products of a (0.25 folded into the tree root) ----
    float ma01 = a[0] * a[1], ma23 = a[2] * a[3], ma45 = a[4] * a[5], ma67 = a[6] * a[7];
    float ma0123 = ma01 * ma23, ma4567 = ma45 * ma67;
    float Pa = ma0123 * ma4567;
    float EA0123 = ma4567 * 0.25f, EA4567 = ma0123 * 0.25f;
    float EA01 = EA0123 * ma23, EA23 = EA0123 * ma01;
    float EA45 = EA4567 * ma67, EA67 = EA4567 * ma45;
    float ea[8];
    ea[0] = EA01 * a[1]; ea[1] = EA01 * a[0];
    ea[2] = EA23 * a[3]; ea[3] = EA23 * a[2];
    ea[4] = EA45 * a[5]; ea[5] = EA45 * a[4];
    ea[6] = EA67 * a[7]; ea[7] = EA67 * a[6];

    // ---- exclusive products of b (0.25 folded) ----
    float mb01 = b[0] * b[1], mb23 = b[2] * b[3], mb45 = b[4] * b[5], mb67 = b[6] * b[7];
    float mb0123 = mb01 * mb23, mb4567 = mb45 * mb67;
    float Pb = mb0123 * mb4567;
    float EB0123 = mb4567 * 0.25f, EB4567 = mb0123 * 0.25f;
    float EB01 = EB0123 * mb23, EB23 = EB0123 * mb01;
    float EB45 = EB4567 * mb67, EB67 = EB4567 * mb45;
    float eb[8];
    eb[0] = EB01 * b[1]; eb[1] = EB01 * b[0];
    eb[2] = EB23 * b[3]; eb[3] = EB23 * b[2];
    eb[4] = EB45 * b[5]; eb[5] = EB45 * b[4];
    eb[6] = EB67 * b[7]; eb[7] = EB67 * b[6];

    float D  = fmaf(0.5f, Pa + Pb, D1);
    float rD = rcp_approx(D);

    float o[8];
#pragma unroll
    for (int d = 0; d < 8; d++) {
        float Bd    = a[d] * b[d];
        float inner = fmaf(b[d], ea[d], a[d] * eb[d]);   // carries the 1/4
        float num   = fmaf(Bd, eS[d], inner);
        o[d] = num * rD;
    }

    __stcs(&o4[2 * p + 0], make_float4(o[0], o[1], o[2], o[3]));
    __stcs(&o4[2 * p + 1], make_float4(o[4], o[5], o[6], o[7]));
}

extern "C" void kernel_launch(void* const* d_in, const int* in_sizes, int n_in,
                              void* d_out, int out_size) {
    const float4* x4 = (const float4*)d_in[0];   // [N, 8] fp32
    float4* o4 = (float4*)d_out;
    int n = in_sizes[0] / 8;
    int block = 256;
    int grid = (n + block - 1) / block;
    e8_quantize_kernel<<<grid, block>>>(x4, o4, n);
}